// round 2
// baseline (speedup 1.0000x reference)
#include <cuda_runtime.h>

#define BS   16
#define NN   1024
#define FIN  128
#define FOUT 64
#define NH   4
#define NEG  0.2f
#define NW   (NN/32)   // 32 adj words per row

// ---- scratch (static device allocations are allowed) ----
__device__ float    g_hp[(size_t)BS*NH*NN*FOUT];   // 16 MB: h_prime fp32
__device__ unsigned g_adj[(size_t)BS*NN*NW];       // 2 MB: adjacency bitmask
__device__ float    g_src [BS*NH*NN];
__device__ float    g_Es  [BS*NH*NN];   // exp(src)
__device__ float    g_E2s [BS*NH*NN];   // exp(0.2*src)
__device__ float    g_dstv[BS*NH*NN];
__device__ float    g_Fd  [BS*NH*NN];   // exp(dst)
__device__ float    g_F2d [BS*NH*NN];   // exp(0.2*dst)

// ---------------------------------------------------------------------------
// Kernel 1: pack adjacency (int32 0/1) into bitmask. One warp per 32-bit word.
// ---------------------------------------------------------------------------
__global__ void pack_adj_kernel(const int* __restrict__ adj) {
    int warp = (blockIdx.x * blockDim.x + threadIdx.x) >> 5;
    int lane = threadIdx.x & 31;
    int v = adj[(size_t)warp * 32 + lane];
    unsigned m = __ballot_sync(0xffffffffu, v != 0);
    if (lane == 0) g_adj[warp] = m;
}

// ---------------------------------------------------------------------------
// Kernel 2: h_prime = h @ w[hd], fused tanh + a_src/a_dst dots + exp tables.
// Block: (n-tile of 32, head, batch). 256 threads: (nl 0..31) x (og 0..7).
// h is read straight from global: the 8 threads of an nl-group hit the same
// address -> broadcast; w (the reuse operand) is staged in shared (32 KB).
// ---------------------------------------------------------------------------
__global__ void __launch_bounds__(256) hp_kernel(
    const float* __restrict__ h, const float* __restrict__ w,
    const float* __restrict__ a_src, const float* __restrict__ a_dst)
{
    int b = blockIdx.z, hd = blockIdx.y, nt = blockIdx.x;
    __shared__ float w_sh[FIN][FOUT];      // 32 KB
    __shared__ float as_sh[FOUT], ad_sh[FOUT];

    int t = threadIdx.x;
    for (int idx = t; idx < FIN * FOUT; idx += 256)
        w_sh[idx >> 6][idx & 63] = w[hd * FIN * FOUT + idx];
    if (t < FOUT) { as_sh[t] = a_src[hd * FOUT + t]; ad_sh[t] = a_dst[hd * FOUT + t]; }
    __syncthreads();

    int nl = t >> 3, og = t & 7;
    int n = nt * 32 + nl;
    const float* hrow = h + ((size_t)b * NN + n) * FIN;

    float acc[8] = {0.f,0.f,0.f,0.f,0.f,0.f,0.f,0.f};
    #pragma unroll 8
    for (int f = 0; f < FIN; f++) {
        float hv = __ldg(hrow + f);
        const float4* wr = (const float4*)&w_sh[f][og * 8];
        float4 w0 = wr[0], w1 = wr[1];
        acc[0] += hv * w0.x; acc[1] += hv * w0.y;
        acc[2] += hv * w0.z; acc[3] += hv * w0.w;
        acc[4] += hv * w1.x; acc[5] += hv * w1.y;
        acc[6] += hv * w1.z; acc[7] += hv * w1.w;
    }

    size_t base = ((size_t)(b * NH + hd) * NN + n) * FOUT + og * 8;
    float4* o4 = (float4*)&g_hp[base];
    o4[0] = make_float4(acc[0], acc[1], acc[2], acc[3]);
    o4[1] = make_float4(acc[4], acc[5], acc[6], acc[7]);

    float ps = 0.f, pd = 0.f;
    #pragma unroll
    for (int k = 0; k < 8; k++) {
        float tv = tanhf(acc[k]);
        ps += tv * as_sh[og * 8 + k];
        pd += tv * ad_sh[og * 8 + k];
    }
    #pragma unroll
    for (int off = 4; off; off >>= 1) {
        ps += __shfl_down_sync(0xffffffffu, ps, off, 8);
        pd += __shfl_down_sync(0xffffffffu, pd, off, 8);
    }
    if (og == 0) {
        int idx = (b * NH + hd) * NN + n;
        g_src[idx]  = ps; g_Es[idx] = expf(ps); g_E2s[idx] = expf(NEG * ps);
        g_dstv[idx] = pd; g_Fd[idx] = expf(pd); g_F2d[idx] = expf(NEG * pd);
    }
}

// ---------------------------------------------------------------------------
// Kernel 3: out[i,:] = (1/S_i) * sum_j P_ij * hp[j,:] + bias
// P_ij = adj ? ((src_i+dst_j>=0) ? Es_i*Fd_j : E2s_i*F2d_j) : 0  (exact)
// Block: (i-tile of 128, head, batch). 256 threads, 4 rows x 8 cols per thread.
// ---------------------------------------------------------------------------
__global__ void __launch_bounds__(256) attn_kernel(
    const float* __restrict__ bias, float* __restrict__ out)
{
    int b = blockIdx.z, hd = blockIdx.y, it = blockIdx.x;
    int i0 = it * 128;
    __shared__ float4   hp_sh[32][16];   // 8 KB: hp tile [32 j][64 o]
    __shared__ float4   dFF[32];         // (dst, Fd, F2d, -) per j
    __shared__ unsigned adj_sh[128];     // 1 word per i-row for this j-tile

    int t = threadIdx.x;
    int ig = t >> 3, og = t & 7;
    int bh = (b * NH + hd) * NN;

    float srcv[4], Es[4], E2s[4], S[4] = {0.f,0.f,0.f,0.f};
    float acc[4][8];
    #pragma unroll
    for (int r = 0; r < 4; r++) {
        int gi = bh + i0 + ig * 4 + r;
        srcv[r] = g_src[gi]; Es[r] = g_Es[gi]; E2s[r] = g_E2s[gi];
        #pragma unroll
        for (int k = 0; k < 8; k++) acc[r][k] = 0.f;
    }

    const float* hp = g_hp + (size_t)bh * FOUT;

    for (int jt = 0; jt < 32; jt++) {
        int j0 = jt * 32;
        #pragma unroll
        for (int idx = t; idx < 512; idx += 256) {
            int j = idx >> 4, c = idx & 15;
            hp_sh[j][c] = ((const float4*)(hp + (size_t)(j0 + j) * FOUT))[c];
        }
        if (t < 32) {
            int gi = bh + j0 + t;
            dFF[t] = make_float4(g_dstv[gi], g_Fd[gi], g_F2d[gi], 0.f);
        }
        if (t >= 128) {
            int ii = t - 128;
            adj_sh[ii] = g_adj[((size_t)b * NN + i0 + ii) * NW + jt];
        }
        __syncthreads();

        unsigned aw[4];
        #pragma unroll
        for (int r = 0; r < 4; r++) aw[r] = adj_sh[ig * 4 + r];

        #pragma unroll 4
        for (int j = 0; j < 32; j++) {
            float4 dv = dFF[j];
            float4 h0 = hp_sh[j][og * 2];
            float4 h1 = hp_sh[j][og * 2 + 1];
            #pragma unroll
            for (int r = 0; r < 4; r++) {
                float x = srcv[r] + dv.x;
                float p = (x >= 0.f) ? Es[r] * dv.y : E2s[r] * dv.z;
                p = ((aw[r] >> j) & 1u) ? p : 0.f;
                S[r] += p;
                acc[r][0] += p * h0.x; acc[r][1] += p * h0.y;
                acc[r][2] += p * h0.z; acc[r][3] += p * h0.w;
                acc[r][4] += p * h1.x; acc[r][5] += p * h1.y;
                acc[r][6] += p * h1.z; acc[r][7] += p * h1.w;
            }
        }
        __syncthreads();
    }

    float bv[8];
    #pragma unroll
    for (int k = 0; k < 8; k++) bv[k] = bias[og * 8 + k];

    #pragma unroll
    for (int r = 0; r < 4; r++) {
        float inv = 1.0f / S[r];
        size_t base = ((size_t)bh + i0 + ig * 4 + r) * FOUT + og * 8;
        float4* o4 = (float4*)&out[base];
        o4[0] = make_float4(acc[r][0]*inv + bv[0], acc[r][1]*inv + bv[1],
                            acc[r][2]*inv + bv[2], acc[r][3]*inv + bv[3]);
        o4[1] = make_float4(acc[r][4]*inv + bv[4], acc[r][5]*inv + bv[5],
                            acc[r][6]*inv + bv[6], acc[r][7]*inv + bv[7]);
    }
}

// ---------------------------------------------------------------------------
extern "C" void kernel_launch(void* const* d_in, const int* in_sizes, int n_in,
                              void* d_out, int out_size)
{
    const float* h     = (const float*)d_in[0];
    const int*   adj   = (const int*)  d_in[1];
    const float* w     = (const float*)d_in[2];
    const float* a_src = (const float*)d_in[3];
    const float* a_dst = (const float*)d_in[4];
    const float* bias  = (const float*)d_in[5];
    float* out = (float*)d_out;

    // 16*1024*32 words, 1 warp per word, 8 warps per block
    pack_adj_kernel<<<(BS * NN * NW) / 8, 256>>>(adj);
    hp_kernel<<<dim3(NN / 32, NH, BS), 256>>>(h, w, a_src, a_dst);
    attn_kernel<<<dim3(NN / 128, NH, BS), 256>>>(bias, out);
}